// round 4
// baseline (speedup 1.0000x reference)
#include <cuda_runtime.h>
#include <cuda_bf16.h>

// Focal loss (2-class) full reduction via sigmoid reformulation:
//   d = x1 - x0, a = -|d|, e = exp(a), s = 1 + e
//   p_max = 1/s, p_min = e/s, lp_max = -log(s), lp_min = a - log(s)
//   loss = A*log(s)*p_min^2 - B*(a - log(s))*p_max^2
//   (A,B) = (oh1,oh0) if x1>=x0 else (oh0,oh1)
//   oh1 = (g>=0.5) ? 0.25 : 0 ; oh0 = (g>=0.5) ? 0.5625 : 0.75
// Single kernel: block partials -> __device__ scratch, last block reduces
// and writes d_out (threadfence-reduction pattern; self-resetting counter
// keeps it deterministic across graph replays).

#define NBLOCKS 1184   // 148 SMs * 8 CTAs: exactly one balanced wave
#define NTHREADS 256

__device__ float g_partials[NBLOCKS];
__device__ unsigned int g_ticket = 0;

__device__ __forceinline__ float rcp_approx(float x) {
    float r;
    asm("rcp.approx.f32 %0, %1;" : "=f"(r) : "f"(x));
    return r;
}

__device__ __forceinline__ float focal_row(float x0, float x1, float g) {
    float d  = x1 - x0;
    float a  = -fabsf(d);          // <= 0
    float e  = __expf(a);          // 1 EX2
    float s  = 1.0f + e;
    float r  = rcp_approx(s);      // 1 MUFU.RCP
    float ls = __logf(s);          // 1 LG2

    float pmax  = r;
    float pmin  = e * r;
    float lpmin = a - ls;

    bool posd = d >= 0.0f;
    bool posg = g >= 0.5f;
    float oh1 = posg ? 0.25f   : 0.0f;
    float oh0 = posg ? 0.5625f : 0.75f;
    float A = posd ? oh1 : oh0;
    float B = posd ? oh0 : oh1;

    float t0 = A * ls;
    float t1 = B * lpmin;
    return fmaf(t0, pmin * pmin, -(t1 * (pmax * pmax)));
}

__device__ __forceinline__ float block_reduce(float v, float* warp_sums) {
    #pragma unroll
    for (int off = 16; off > 0; off >>= 1)
        v += __shfl_xor_sync(0xFFFFFFFFu, v, off);
    int lane = threadIdx.x & 31;
    int wid  = threadIdx.x >> 5;
    if (lane == 0) warp_sums[wid] = v;
    __syncthreads();
    if (wid == 0) {
        v = (lane < NTHREADS / 32) ? warp_sums[lane] : 0.0f;
        #pragma unroll
        for (int off = 4; off > 0; off >>= 1)
            v += __shfl_xor_sync(0xFFFFFFFFu, v, off);
    }
    return v;  // valid in warp 0
}

__global__ void __launch_bounds__(NTHREADS, 8)
focal_loss_kernel(const float* __restrict__ pred,   // [N, 2] f32
                  const float* __restrict__ gold,   // [N]    f32
                  float* __restrict__ out,
                  int n)                            // N rows
{
    const float4* __restrict__ pred4 = (const float4*)pred;  // N/2 float4
    const float4* __restrict__ gold4 = (const float4*)gold;  // N/4 float4

    float acc = 0.0f;

    int n8 = n >> 3;                       // iterations of 8 rows
    int stride = gridDim.x * blockDim.x;
    int tid = blockIdx.x * blockDim.x + threadIdx.x;

    for (int i = tid; i < n8; i += stride) {
        // 8 rows per iteration: 4 float4 pred + 2 float4 gold, streaming loads
        float4 pa = __ldcs(&pred4[4 * i]);
        float4 pb = __ldcs(&pred4[4 * i + 1]);
        float4 pc = __ldcs(&pred4[4 * i + 2]);
        float4 pd = __ldcs(&pred4[4 * i + 3]);
        float4 ga = __ldcs(&gold4[2 * i]);
        float4 gb = __ldcs(&gold4[2 * i + 1]);

        acc += focal_row(pa.x, pa.y, ga.x);
        acc += focal_row(pa.z, pa.w, ga.y);
        acc += focal_row(pb.x, pb.y, ga.z);
        acc += focal_row(pb.z, pb.w, ga.w);
        acc += focal_row(pc.x, pc.y, gb.x);
        acc += focal_row(pc.z, pc.w, gb.y);
        acc += focal_row(pd.x, pd.y, gb.z);
        acc += focal_row(pd.z, pd.w, gb.w);
    }

    // Scalar tail for n % 8 rows (no-op when N divisible by 8)
    int tail_start = n8 << 3;
    for (int r = tail_start + tid; r < n; r += stride) {
        acc += focal_row(pred[2 * r], pred[2 * r + 1], gold[r]);
    }

    __shared__ float warp_sums[NTHREADS / 32];
    float bsum = block_reduce(acc, warp_sums);

    // Publish block partial; last block finishes the reduction.
    __shared__ int is_last;
    if (threadIdx.x == 0) {
        g_partials[blockIdx.x] = bsum;
        __threadfence();
        unsigned int t = atomicAdd(&g_ticket, 1u);
        is_last = (t == gridDim.x - 1) ? 1 : 0;
    }
    __syncthreads();

    if (is_last) {
        float v = 0.0f;
        for (int i = threadIdx.x; i < gridDim.x; i += NTHREADS)
            v += g_partials[i];
        __syncthreads();  // reuse warp_sums safely
        float total = block_reduce(v, warp_sums);
        if (threadIdx.x == 0) {
            out[0] = total;
            g_ticket = 0;   // reset for next graph replay
        }
    }
}

extern "C" void kernel_launch(void* const* d_in, const int* in_sizes, int n_in,
                              void* d_out, int out_size) {
    // Auto-detect input order by size: pred has 2*N elements, gold has N.
    const float* pred;
    const float* gold;
    int n;
    if (n_in >= 2 && in_sizes[0] >= in_sizes[1]) {
        pred = (const float*)d_in[0];
        gold = (const float*)d_in[1];
        n = in_sizes[1];
    } else {
        pred = (const float*)d_in[1];
        gold = (const float*)d_in[0];
        n = in_sizes[0];
    }
    float* out = (float*)d_out;

    focal_loss_kernel<<<NBLOCKS, NTHREADS>>>(pred, gold, out, n);
}

// round 5
// speedup vs baseline: 1.0218x; 1.0218x over previous
#include <cuda_runtime.h>
#include <cuda_bf16.h>

// Focal loss (2-class) full reduction via sigmoid reformulation:
//   d = x1 - x0, a = -|d|, e = exp(a), s = 1 + e
//   p_max = 1/s, p_min = e/s, lp_max = -log(s), lp_min = a - log(s)
//   loss = A*log(s)*p_min^2 - B*(a - log(s))*p_max^2
//   (A,B) = (oh1,oh0) if x1>=x0 else (oh0,oh1)
//   oh1 = (g>=0.5) ? 0.25 : 0 ; oh0 = (g>=0.5) ? 0.5625 : 0.75
// Single kernel: block partials -> __device__ scratch, last block reduces
// and writes d_out (threadfence-reduction pattern; self-resetting counter
// keeps it deterministic across graph replays).

#define NBLOCKS 1184   // 148 SMs * 8 CTAs: exactly one balanced wave
#define NTHREADS 256

__device__ float g_partials[NBLOCKS];
__device__ unsigned int g_ticket = 0;

__device__ __forceinline__ float rcp_approx(float x) {
    float r;
    asm("rcp.approx.f32 %0, %1;" : "=f"(r) : "f"(x));
    return r;
}

__device__ __forceinline__ float focal_row(float x0, float x1, float g) {
    float d  = x1 - x0;
    float a  = -fabsf(d);          // <= 0
    float e  = __expf(a);          // 1 EX2
    float s  = 1.0f + e;
    float r  = rcp_approx(s);      // 1 MUFU.RCP
    float ls = __logf(s);          // 1 LG2

    float pmax  = r;
    float pmin  = e * r;
    float lpmin = a - ls;

    bool posd = d >= 0.0f;
    bool posg = g >= 0.5f;
    float oh1 = posg ? 0.25f   : 0.0f;
    float oh0 = posg ? 0.5625f : 0.75f;
    float A = posd ? oh1 : oh0;
    float B = posd ? oh0 : oh1;

    float t0 = A * ls;
    float t1 = B * lpmin;
    return fmaf(t0, pmin * pmin, -(t1 * (pmax * pmax)));
}

__device__ __forceinline__ float block_reduce(float v, float* warp_sums) {
    #pragma unroll
    for (int off = 16; off > 0; off >>= 1)
        v += __shfl_xor_sync(0xFFFFFFFFu, v, off);
    int lane = threadIdx.x & 31;
    int wid  = threadIdx.x >> 5;
    if (lane == 0) warp_sums[wid] = v;
    __syncthreads();
    if (wid == 0) {
        v = (lane < NTHREADS / 32) ? warp_sums[lane] : 0.0f;
        #pragma unroll
        for (int off = 4; off > 0; off >>= 1)
            v += __shfl_xor_sync(0xFFFFFFFFu, v, off);
    }
    return v;  // valid in warp 0
}

__global__ void __launch_bounds__(NTHREADS, 8)
focal_loss_kernel(const float* __restrict__ pred,   // [N, 2] f32
                  const float* __restrict__ gold,   // [N]    f32
                  float* __restrict__ out,
                  int n)                            // N rows
{
    const float4* __restrict__ pred4 = (const float4*)pred;  // N/2 float4
    const float4* __restrict__ gold4 = (const float4*)gold;  // N/4 float4

    float acc = 0.0f;

    int n8 = n >> 3;                       // iterations of 8 rows
    int stride = gridDim.x * blockDim.x;
    int tid = blockIdx.x * blockDim.x + threadIdx.x;

    for (int i = tid; i < n8; i += stride) {
        // 8 rows per iteration: 4 float4 pred + 2 float4 gold, streaming loads
        float4 pa = __ldcs(&pred4[4 * i]);
        float4 pb = __ldcs(&pred4[4 * i + 1]);
        float4 pc = __ldcs(&pred4[4 * i + 2]);
        float4 pd = __ldcs(&pred4[4 * i + 3]);
        float4 ga = __ldcs(&gold4[2 * i]);
        float4 gb = __ldcs(&gold4[2 * i + 1]);

        acc += focal_row(pa.x, pa.y, ga.x);
        acc += focal_row(pa.z, pa.w, ga.y);
        acc += focal_row(pb.x, pb.y, ga.z);
        acc += focal_row(pb.z, pb.w, ga.w);
        acc += focal_row(pc.x, pc.y, gb.x);
        acc += focal_row(pc.z, pc.w, gb.y);
        acc += focal_row(pd.x, pd.y, gb.z);
        acc += focal_row(pd.z, pd.w, gb.w);
    }

    // Scalar tail for n % 8 rows (no-op when N divisible by 8)
    int tail_start = n8 << 3;
    for (int r = tail_start + tid; r < n; r += stride) {
        acc += focal_row(pred[2 * r], pred[2 * r + 1], gold[r]);
    }

    __shared__ float warp_sums[NTHREADS / 32];
    float bsum = block_reduce(acc, warp_sums);

    // Publish block partial; last block finishes the reduction.
    __shared__ int is_last;
    if (threadIdx.x == 0) {
        g_partials[blockIdx.x] = bsum;
        __threadfence();
        unsigned int t = atomicAdd(&g_ticket, 1u);
        is_last = (t == gridDim.x - 1) ? 1 : 0;
    }
    __syncthreads();

    if (is_last) {
        float v = 0.0f;
        for (int i = threadIdx.x; i < gridDim.x; i += NTHREADS)
            v += g_partials[i];
        __syncthreads();  // reuse warp_sums safely
        float total = block_reduce(v, warp_sums);
        if (threadIdx.x == 0) {
            out[0] = total;
            g_ticket = 0;   // reset for next graph replay
        }
    }
}

extern "C" void kernel_launch(void* const* d_in, const int* in_sizes, int n_in,
                              void* d_out, int out_size) {
    // Auto-detect input order by size: pred has 2*N elements, gold has N.
    const float* pred;
    const float* gold;
    int n;
    if (n_in >= 2 && in_sizes[0] >= in_sizes[1]) {
        pred = (const float*)d_in[0];
        gold = (const float*)d_in[1];
        n = in_sizes[1];
    } else {
        pred = (const float*)d_in[1];
        gold = (const float*)d_in[0];
        n = in_sizes[0];
    }
    float* out = (float*)d_out;

    focal_loss_kernel<<<NBLOCKS, NTHREADS>>>(pred, gold, out, n);
}

// round 6
// speedup vs baseline: 1.0262x; 1.0042x over previous
#include <cuda_runtime.h>
#include <cuda_bf16.h>

// Focal loss (2-class) full reduction via sigmoid reformulation:
//   d = x1 - x0, a = -|d|, e = exp(a), s = 1 + e
//   p_max = 1/s, p_min = e/s, lp_max = -log(s), lp_min = a - log(s)
//   loss = A*log(s)*p_min^2 - B*(a - log(s))*p_max^2
//   (A,B) = (oh1,oh0) if x1>=x0 else (oh0,oh1)
//   oh1 = (g>=0.5) ? 0.25 : 0 ; oh0 = (g>=0.5) ? 0.5625 : 0.75
// Single kernel: block partials -> __device__ scratch, last block reduces
// and writes d_out (threadfence-reduction pattern; self-resetting counter
// keeps it deterministic across graph replays).

#define NBLOCKS 1184   // 148 SMs * 8 CTAs: exactly one balanced wave
#define NTHREADS 256

__device__ float g_partials[NBLOCKS];
__device__ unsigned int g_ticket = 0;

__device__ __forceinline__ float rcp_approx(float x) {
    float r;
    asm("rcp.approx.f32 %0, %1;" : "=f"(r) : "f"(x));
    return r;
}

__device__ __forceinline__ float focal_row(float x0, float x1, float g) {
    float d  = x1 - x0;
    float a  = -fabsf(d);          // <= 0
    float e  = __expf(a);          // 1 EX2
    float s  = 1.0f + e;
    float r  = rcp_approx(s);      // 1 MUFU.RCP
    float ls = __logf(s);          // 1 LG2

    float pmax  = r;
    float pmin  = e * r;
    float lpmin = a - ls;

    bool posd = d >= 0.0f;
    bool posg = g >= 0.5f;
    float oh1 = posg ? 0.25f   : 0.0f;
    float oh0 = posg ? 0.5625f : 0.75f;
    float A = posd ? oh1 : oh0;
    float B = posd ? oh0 : oh1;

    float t0 = A * ls;
    float t1 = B * lpmin;
    return fmaf(t0, pmin * pmin, -(t1 * (pmax * pmax)));
}

__device__ __forceinline__ float block_reduce(float v, float* warp_sums) {
    #pragma unroll
    for (int off = 16; off > 0; off >>= 1)
        v += __shfl_xor_sync(0xFFFFFFFFu, v, off);
    int lane = threadIdx.x & 31;
    int wid  = threadIdx.x >> 5;
    if (lane == 0) warp_sums[wid] = v;
    __syncthreads();
    if (wid == 0) {
        v = (lane < NTHREADS / 32) ? warp_sums[lane] : 0.0f;
        #pragma unroll
        for (int off = 4; off > 0; off >>= 1)
            v += __shfl_xor_sync(0xFFFFFFFFu, v, off);
    }
    return v;  // valid in warp 0
}

__global__ void __launch_bounds__(NTHREADS, 8)
focal_loss_kernel(const float* __restrict__ pred,   // [N, 2] f32
                  const float* __restrict__ gold,   // [N]    f32
                  float* __restrict__ out,
                  int n)                            // N rows
{
    const float4* __restrict__ pred4 = (const float4*)pred;  // N/2 float4
    const float4* __restrict__ gold4 = (const float4*)gold;  // N/4 float4

    float acc = 0.0f;

    int n8 = n >> 3;                       // iterations of 8 rows
    int stride = gridDim.x * blockDim.x;
    int tid = blockIdx.x * blockDim.x + threadIdx.x;

    for (int i = tid; i < n8; i += stride) {
        // 8 rows per iteration: 4 float4 pred + 2 float4 gold, streaming loads
        float4 pa = __ldcs(&pred4[4 * i]);
        float4 pb = __ldcs(&pred4[4 * i + 1]);
        float4 pc = __ldcs(&pred4[4 * i + 2]);
        float4 pd = __ldcs(&pred4[4 * i + 3]);
        float4 ga = __ldcs(&gold4[2 * i]);
        float4 gb = __ldcs(&gold4[2 * i + 1]);

        acc += focal_row(pa.x, pa.y, ga.x);
        acc += focal_row(pa.z, pa.w, ga.y);
        acc += focal_row(pb.x, pb.y, ga.z);
        acc += focal_row(pb.z, pb.w, ga.w);
        acc += focal_row(pc.x, pc.y, gb.x);
        acc += focal_row(pc.z, pc.w, gb.y);
        acc += focal_row(pd.x, pd.y, gb.z);
        acc += focal_row(pd.z, pd.w, gb.w);
    }

    // Scalar tail for n % 8 rows (no-op when N divisible by 8)
    int tail_start = n8 << 3;
    for (int r = tail_start + tid; r < n; r += stride) {
        acc += focal_row(pred[2 * r], pred[2 * r + 1], gold[r]);
    }

    __shared__ float warp_sums[NTHREADS / 32];
    float bsum = block_reduce(acc, warp_sums);

    // Publish block partial; last block finishes the reduction.
    __shared__ int is_last;
    if (threadIdx.x == 0) {
        g_partials[blockIdx.x] = bsum;
        __threadfence();
        unsigned int t = atomicAdd(&g_ticket, 1u);
        is_last = (t == gridDim.x - 1) ? 1 : 0;
    }
    __syncthreads();

    if (is_last) {
        float v = 0.0f;
        for (int i = threadIdx.x; i < gridDim.x; i += NTHREADS)
            v += g_partials[i];
        __syncthreads();  // reuse warp_sums safely
        float total = block_reduce(v, warp_sums);
        if (threadIdx.x == 0) {
            out[0] = total;
            g_ticket = 0;   // reset for next graph replay
        }
    }
}

extern "C" void kernel_launch(void* const* d_in, const int* in_sizes, int n_in,
                              void* d_out, int out_size) {
    // Auto-detect input order by size: pred has 2*N elements, gold has N.
    const float* pred;
    const float* gold;
    int n;
    if (n_in >= 2 && in_sizes[0] >= in_sizes[1]) {
        pred = (const float*)d_in[0];
        gold = (const float*)d_in[1];
        n = in_sizes[1];
    } else {
        pred = (const float*)d_in[1];
        gold = (const float*)d_in[0];
        n = in_sizes[0];
    }
    float* out = (float*)d_out;

    focal_loss_kernel<<<NBLOCKS, NTHREADS>>>(pred, gold, out, n);
}